// round 15
// baseline (speedup 1.0000x reference)
#include <cuda_runtime.h>
#include <cuda_bf16.h>

#define SEQ   8192
#define DIM   2048
#define H     16
#define HD    128           // head dim
#define PDIM  512           // proj dim
#define NCH   64            // weighted-sum chunks (128 rows each)
#define WROWS 128           // rows per wsum chunk
#define LROWS 32            // rows per logits block
#define NSEG  (SEQ / LROWS) // softmax partial segments = 256
#define CSPLIT 8            // k_ured chunk-split factor

// ---------------- scratch (device globals; no allocation allowed) ----------
__device__ float g_qprojH[H * DIM];          // [h][j], pre-scaled by 1/sqrt(HD)
__device__ float g_logits[SEQ * H];          // [s][h]
__device__ float g_pm[NSEG * H];             // per-seg max
__device__ float g_pz[NSEG * H];             // per-seg sumexp
__device__ float g_upart[(size_t)NCH * H * DIM]; // per-chunk weighted sums
__device__ float g_u2[CSPLIT * H * DIM];     // 8-way partial u
__device__ float g_x1[DIM];
__device__ float g_h1[PDIM];
__device__ float g_x1out[DIM];

// ---------------- f32x2 packed helpers -------------------------------------
union F2U { unsigned long long u; float2 f; };

__device__ __forceinline__ void ffma2(unsigned long long& d,
                                      unsigned long long a,
                                      unsigned long long b) {
    asm("fma.rn.f32x2 %0, %1, %2, %0;" : "+l"(d) : "l"(a), "l"(b));
}
__device__ __forceinline__ void addf32x2(unsigned long long& d, unsigned long long a) {
    asm("add.rn.f32x2 %0, %0, %1;" : "+l"(d) : "l"(a));
}
__device__ __forceinline__ unsigned long long pack2(float lo, float hi) {
    unsigned long long r;
    asm("mov.b64 %0, {%1, %2};" : "=l"(r) : "f"(lo), "f"(hi));
    return r;
}
__device__ __forceinline__ float f4el(const float4& v, int e) {
    return e == 0 ? v.x : e == 1 ? v.y : e == 2 ? v.z : v.w;
}

__device__ __forceinline__ float blockReduceSum(float v) {
    __shared__ float sm[32];
    __syncthreads();
    int lane = threadIdx.x & 31, w = threadIdx.x >> 5;
    #pragma unroll
    for (int o = 16; o > 0; o >>= 1) v += __shfl_xor_sync(0xffffffffu, v, o);
    if (lane == 0) sm[w] = v;
    __syncthreads();
    int nw = blockDim.x >> 5;
    v = (threadIdx.x < nw) ? sm[threadIdx.x] : 0.f;
    if (w == 0) {
        #pragma unroll
        for (int o = 16; o > 0; o >>= 1) v += __shfl_xor_sync(0xffffffffu, v, o);
        if (lane == 0) sm[0] = v;
    }
    __syncthreads();
    return sm[0];
}

__device__ __forceinline__ float warpReduceSum(float v) {
    #pragma unroll
    for (int o = 16; o > 0; o >>= 1) v += __shfl_xor_sync(0xffffffffu, v, o);
    return v;
}

// ---------------- K1: qprojH[h][j] = (1/sqrt(HD)) * q[h] . W_k[h][:,j] -----
__global__ void k_qproj(const float* __restrict__ q, const float* __restrict__ Wkv) {
    int h  = blockIdx.x >> 4;
    int jb = blockIdx.x & 15;
    int j  = jb * 128 + threadIdx.x;
    __shared__ float sq[HD];
    sq[threadIdx.x] = q[h * HD + threadIdx.x];
    __syncthreads();
    float acc = 0.f;
    #pragma unroll 8
    for (int d = 0; d < HD; d++)
        acc += sq[d] * Wkv[(size_t)(h * HD + d) * DIM + j];
    g_qprojH[h * DIM + j] = acc * 0.08838834764831845f; // 1/sqrt(128)
}

// ---------------- K2: logits + per-block softmax partials ------------------
// 256 blocks x 256 threads. 8 warps = 4 warp-pairs; pair owns 8 rows;
// warp covers 8 heads. qproj pre-duplicated (w,w) in 256-col smem tiles
// (32 KB), processed in two 128-col register sub-passes -> HALF the barriers.
__global__ void __launch_bounds__(256, 2) k_logits(const float* __restrict__ x) {
    __shared__ float2 qs2[H][4][64];    // 32 KB per 256-col tile
    __shared__ float spm[8][8], spz[8][8];
    int t = threadIdx.x, lane = t & 31, warp = t >> 5;
    int pair = warp >> 1, hbase = (warp & 1) * 8;
    int row0 = blockIdx.x * LROWS + pair * 8;

    unsigned long long acc[8][4];       // [head][row-pair]
    #pragma unroll
    for (int hh = 0; hh < 8; hh++)
        #pragma unroll
        for (int p = 0; p < 4; p++) acc[hh][p] = 0ull;

    const float4* x4 = (const float4*)x;
    const float4* qp4 = (const float4*)g_qprojH;

    for (int jt4 = 0; jt4 < DIM / 4; jt4 += 64) {   // 8 tiles of 256 cols
        __syncthreads();
        #pragma unroll
        for (int r = 0; r < 4; r++) {
            int idx = t + r * 256;      // 0..1023 -> (h, 64 float4)
            int h = idx >> 6;
            int jj = idx & 63;
            float4 v = __ldg(qp4 + (size_t)h * (DIM / 4) + jt4 + jj);
            qs2[h][0][jj] = make_float2(v.x, v.x);
            qs2[h][1][jj] = make_float2(v.y, v.y);
            qs2[h][2][jj] = make_float2(v.z, v.z);
            qs2[h][3][jj] = make_float2(v.w, v.w);
        }
        __syncthreads();
        #pragma unroll
        for (int half = 0; half < 2; half++) {
            int off = half * 32;
            float4 xv[8];
            #pragma unroll
            for (int rr = 0; rr < 8; rr++)
                xv[rr] = __ldg(x4 + (size_t)(row0 + rr) * (DIM / 4)
                               + jt4 + off + lane);
            #pragma unroll
            for (int e = 0; e < 4; e++) {
                unsigned long long xp[4];
                #pragma unroll
                for (int p = 0; p < 4; p++)
                    xp[p] = pack2(f4el(xv[2 * p], e), f4el(xv[2 * p + 1], e));
                #pragma unroll
                for (int hh = 0; hh < 8; hh++) {
                    unsigned long long wp =
                        *(const unsigned long long*)&qs2[hbase + hh][e][off + lane];
                    ffma2(acc[hh][0], wp, xp[0]);
                    ffma2(acc[hh][1], wp, xp[1]);
                    ffma2(acc[hh][2], wp, xp[2]);
                    ffma2(acc[hh][3], wp, xp[3]);
                }
            }
        }
    }
    // shuffle-reduce; lane hh keeps head hbase+hh's 4 row-pairs
    unsigned long long keep[4];
    #pragma unroll
    for (int p = 0; p < 4; p++) keep[p] = 0ull;
    #pragma unroll
    for (int hh = 0; hh < 8; hh++) {
        unsigned long long v0 = acc[hh][0], v1 = acc[hh][1];
        unsigned long long v2 = acc[hh][2], v3 = acc[hh][3];
        #pragma unroll
        for (int o = 16; o > 0; o >>= 1) {
            addf32x2(v0, __shfl_xor_sync(0xffffffffu, v0, o));
            addf32x2(v1, __shfl_xor_sync(0xffffffffu, v1, o));
            addf32x2(v2, __shfl_xor_sync(0xffffffffu, v2, o));
            addf32x2(v3, __shfl_xor_sync(0xffffffffu, v3, o));
        }
        if (lane == hh) { keep[0] = v0; keep[1] = v1; keep[2] = v2; keep[3] = v3; }
    }
    if (lane < 8) {
        int h = hbase + lane;
        float r[8];
        #pragma unroll
        for (int p = 0; p < 4; p++) {
            F2U u; u.u = keep[p];
            r[2 * p] = u.f.x; r[2 * p + 1] = u.f.y;
        }
        float m = r[0];
        #pragma unroll
        for (int rr = 1; rr < 8; rr++) m = fmaxf(m, r[rr]);
        float z = 0.f;
        #pragma unroll
        for (int rr = 0; rr < 8; rr++) {
            g_logits[(size_t)(row0 + rr) * H + h] = r[rr];
            z += __expf(r[rr] - m);
        }
        spm[warp][lane] = m;
        spz[warp][lane] = z;
    }
    __syncthreads();
    if (t < H) {                        // merge 4 pairs -> per-block partial
        int hgc = t >> 3, hl = t & 7;
        float m = -3.0e38f, z = 0.f;
        #pragma unroll
        for (int p = 0; p < 4; p++) {
            int w = p * 2 + hgc;
            float mw = spm[w][hl], zw = spz[w][hl];
            float nm = fmaxf(m, mw);
            z = z * __expf(m - nm) + zw * __expf(mw - nm);
            m = nm;
        }
        g_pm[blockIdx.x * H + t] = m;
        g_pz[blockIdx.x * H + t] = z;
    }
}

// ---------------- K3: u_part[c][h][j] = sum_{s in chunk} attn[s][h]*x[s][j]
// grid (4, 64): blockIdx.x = (head-half<<1)|col-tile; 256 threads, 8 heads
// per block; 3 blocks/SM via launch_bounds. 2 rows/iter inner loop.
__global__ void __launch_bounds__(256, 3) k_wsum(const float* __restrict__ x) {
    __shared__ float sa[WROWS * H];     // 128 x 16 = 8 KB normalized weights
    __shared__ float sm_m[H], sm_inv[H];
    __shared__ float cm[256], cz[256];
    int t = threadIdx.x;
    int cx = blockIdx.x & 1, hg = blockIdx.x >> 1, hbase = hg * 8;

    // stage 1: each thread merges NSEG/16 = 16 segment partials for one head
    {
        int h = t & 15, grp = t >> 4;
        float m = -3.0e38f, z = 0.f;
        #pragma unroll 4
        for (int k = 0; k < NSEG / 16; k++) {
            int seg = grp * (NSEG / 16) + k;
            float mw = g_pm[seg * H + h], zw = g_pz[seg * H + h];
            float nm = fmaxf(m, mw);
            z = z * __expf(m - nm) + zw * __expf(mw - nm);
            m = nm;
        }
        cm[t] = m; cz[t] = z;
    }
    __syncthreads();
    if (t < H) {                        // stage 2: merge the 16 groups
        float m = cm[t], z = cz[t];
        #pragma unroll
        for (int g = 1; g < 16; g++) {
            float mw = cm[g * 16 + t], zw = cz[g * 16 + t];
            float nm = fmaxf(m, mw);
            z = z * __expf(m - nm) + zw * __expf(mw - nm);
            m = nm;
        }
        sm_m[t] = m; sm_inv[t] = 1.f / z;
    }
    __syncthreads();

    int s0 = blockIdx.y * WROWS;
    #pragma unroll
    for (int k = 0; k < 2; k++) {       // weights: 2048 floats = 512 float4
        int idx = t + k * 256;
        float4 l = __ldg((const float4*)(g_logits + (size_t)s0 * H) + idx);
        int h0 = (idx & 3) * 4;
        float4 w;
        w.x = __expf(l.x - sm_m[h0 + 0]) * sm_inv[h0 + 0];
        w.y = __expf(l.y - sm_m[h0 + 1]) * sm_inv[h0 + 1];
        w.z = __expf(l.z - sm_m[h0 + 2]) * sm_inv[h0 + 2];
        w.w = __expf(l.w - sm_m[h0 + 3]) * sm_inv[h0 + 3];
        ((float4*)sa)[idx] = w;
    }
    __syncthreads();

    int j4 = cx * 256 + t;
    unsigned long long acc[4][4];       // [head-pair within half][component]
    #pragma unroll
    for (int hp = 0; hp < 4; hp++)
        #pragma unroll
        for (int c = 0; c < 4; c++) acc[hp][c] = 0ull;

    const float4* x4 = (const float4*)x;
    #pragma unroll 2
    for (int r = 0; r < WROWS; r += 2) {
        float4 xa = __ldg(x4 + (size_t)(s0 + r + 0) * (DIM / 4) + j4);
        float4 xb = __ldg(x4 + (size_t)(s0 + r + 1) * (DIM / 4) + j4);
        unsigned long long xpa[4], xpb[4];
        xpa[0] = pack2(xa.x, xa.x); xpb[0] = pack2(xb.x, xb.x);
        xpa[1] = pack2(xa.y, xa.y); xpb[1] = pack2(xb.y, xb.y);
        xpa[2] = pack2(xa.z, xa.z); xpb[2] = pack2(xb.z, xb.z);
        xpa[3] = pack2(xa.w, xa.w); xpb[3] = pack2(xb.w, xb.w);
        const float2* ar0 = (const float2*)(sa + (r + 0) * H + hbase);
        const float2* ar1 = (const float2*)(sa + (r + 1) * H + hbase);
        #pragma unroll
        for (int hp = 0; hp < 4; hp++) {
            float2 a0 = ar0[hp];        // broadcast LDS.64
            float2 a1 = ar1[hp];
            unsigned long long ap0 = pack2(a0.x, a0.y);
            unsigned long long ap1 = pack2(a1.x, a1.y);
            ffma2(acc[hp][0], ap0, xpa[0]);
            ffma2(acc[hp][1], ap0, xpa[1]);
            ffma2(acc[hp][2], ap0, xpa[2]);
            ffma2(acc[hp][3], ap0, xpa[3]);
            ffma2(acc[hp][0], ap1, xpb[0]);
            ffma2(acc[hp][1], ap1, xpb[1]);
            ffma2(acc[hp][2], ap1, xpb[2]);
            ffma2(acc[hp][3], ap1, xpb[3]);
        }
    }
    float* up = g_upart + (size_t)blockIdx.y * (H * DIM);
    #pragma unroll
    for (int hp = 0; hp < 4; hp++) {
        F2U u0, u1, u2, u3;
        u0.u = acc[hp][0]; u1.u = acc[hp][1]; u2.u = acc[hp][2]; u3.u = acc[hp][3];
        float4 lo = make_float4(u0.f.x, u1.f.x, u2.f.x, u3.f.x);
        float4 hi = make_float4(u0.f.y, u1.f.y, u2.f.y, u3.f.y);
        ((float4*)(up + (size_t)(hbase + 2 * hp + 0) * DIM))[j4] = lo;
        ((float4*)(up + (size_t)(hbase + 2 * hp + 1) * DIM))[j4] = hi;
    }
}

// ---------------- K4: u2[p][i4] = sum_{c in part p} u_part[c][i4] ----------
// grid (32, CSPLIT=8) x 256 threads; float4 loads
__global__ void k_ured() {
    int i4 = blockIdx.x * 256 + threadIdx.x;   // float4 index 0..H*DIM/4-1
    int c0 = blockIdx.y * (NCH / CSPLIT);
    const float4* up4 = (const float4*)g_upart;
    float4 s = make_float4(0.f, 0.f, 0.f, 0.f);
    #pragma unroll 8
    for (int c = 0; c < NCH / CSPLIT; c++) {
        float4 a = up4[(size_t)(c0 + c) * (H * DIM / 4) + i4];
        s.x += a.x; s.y += a.y; s.z += a.z; s.w += a.w;
    }
    ((float4*)g_u2)[(size_t)blockIdx.y * (H * DIM / 4) + i4] = s;
}

// ---------------- K5: x1[r] = b_v[r] + W_v[r] . u[r>>7] --------------------
__global__ void __launch_bounds__(128) k_xv(const float* __restrict__ Wkv,
                                            const float* __restrict__ bkv) {
    __shared__ float su[DIM];
    int t = threadIdx.x, lane = t & 31, warp = t >> 5;
    int r0 = blockIdx.x * 4;
    int h  = r0 >> 7;                   // 4 | 128 so all rows share the head
    #pragma unroll
    for (int i = 0; i < 4; i++) {
        int idx = t + i * 128;          // 512 float4 total
        float4 s = make_float4(0.f, 0.f, 0.f, 0.f);
        #pragma unroll
        for (int p = 0; p < CSPLIT; p++) {
            float4 a = *((const float4*)(g_u2 + (size_t)p * (H * DIM)
                                         + (size_t)h * DIM) + idx);
            s.x += a.x; s.y += a.y; s.z += a.z; s.w += a.w;
        }
        ((float4*)su)[idx] = s;
    }
    __syncthreads();
    int r = r0 + warp;
    const float4* w4 = (const float4*)(Wkv + (size_t)(DIM + r) * DIM);
    float acc = 0.f;
    #pragma unroll
    for (int i = 0; i < 16; i++) {
        float4 a = __ldg(w4 + i * 32 + lane);
        float4 b = ((float4*)su)[i * 32 + lane];
        acc += a.x * b.x + a.y * b.y + a.z * b.z + a.w * b.w;
    }
    acc = warpReduceSum(acc);
    if (lane == 0) g_x1[r] = acc + bkv[DIM + r];
}

// ---------------- K6: h1[r] = b_p1[r] + W_p1[r] . x1 -----------------------
__global__ void __launch_bounds__(256) k_mlp1(const float* __restrict__ Wp1,
                                              const float* __restrict__ bp1) {
    __shared__ float sv[DIM];
    int t = threadIdx.x, lane = t & 31, warp = t >> 5;
    #pragma unroll
    for (int i = 0; i < 2; i++)
        ((float4*)sv)[t + i * 256] = *((const float4*)g_x1 + t + i * 256);
    __syncthreads();
    int r = blockIdx.x * 8 + warp;
    const float4* w4 = (const float4*)(Wp1 + (size_t)r * DIM);
    float acc = 0.f;
    #pragma unroll
    for (int i = 0; i < 16; i++) {
        float4 a = __ldg(w4 + i * 32 + lane);
        float4 b = ((float4*)sv)[i * 32 + lane];
        acc += a.x * b.x + a.y * b.y + a.z * b.z + a.w * b.w;
    }
    acc = warpReduceSum(acc);
    if (lane == 0) g_h1[r] = acc + bp1[r];
}

// ---------------- K7: LN(h1) -> relu -> x1out = W_p2 . g + b_p2 ------------
__global__ void __launch_bounds__(256) k_mlp2(const float* __restrict__ lnw,
                                              const float* __restrict__ lnb,
                                              const float* __restrict__ Wp2,
                                              const float* __restrict__ bp2) {
    __shared__ float sg[PDIM];
    int t = threadIdx.x, lane = t & 31, warp = t >> 5;
    float v0 = g_h1[t], v1 = g_h1[t + 256];
    float mu = blockReduceSum(v0 + v1) * (1.f / PDIM);
    float d0 = v0 - mu, d1 = v1 - mu;
    float var = blockReduceSum(d0 * d0 + d1 * d1) * (1.f / PDIM);
    float rs = rsqrtf(var + 1e-5f);
    sg[t]       = fmaxf(d0 * rs * lnw[t]       + lnb[t],       0.f);
    sg[t + 256] = fmaxf(d1 * rs * lnw[t + 256] + lnb[t + 256], 0.f);
    __syncthreads();
    int r = blockIdx.x * 8 + warp;
    const float4* w4 = (const float4*)(Wp2 + (size_t)r * PDIM);
    float acc = 0.f;
    #pragma unroll
    for (int i = 0; i < 4; i++) {
        float4 a = __ldg(w4 + i * 32 + lane);
        float4 b = ((float4*)sg)[i * 32 + lane];
        acc += a.x * b.x + a.y * b.y + a.z * b.z + a.w * b.w;
    }
    acc = warpReduceSum(acc);
    if (lane == 0) g_x1out[r] = acc + bp2[r];
}

// ---------------- K8: out[s][j] = x[s][j] + x1out[j] -----------------------
__global__ void k_resid(const float* __restrict__ x, float* __restrict__ out) {
    size_t base = (size_t)blockIdx.x * 512 + threadIdx.x;
    #pragma unroll
    for (int r = 0; r < 2; r++) {
        size_t i = base + r * 256;
        float4 xv = ((const float4*)x)[i];
        float4 a  = __ldg((const float4*)g_x1out + (i & (DIM / 4 - 1)));
        xv.x += a.x; xv.y += a.y; xv.z += a.z; xv.w += a.w;
        ((float4*)out)[i] = xv;
    }
}

extern "C" void kernel_launch(void* const* d_in, const int* in_sizes, int n_in,
                              void* d_out, int out_size) {
    const float* x    = (const float*)d_in[0];
    const float* q    = (const float*)d_in[1];
    const float* Wkv  = (const float*)d_in[2];
    const float* bkv  = (const float*)d_in[3];
    const float* Wp1  = (const float*)d_in[4];
    const float* bp1  = (const float*)d_in[5];
    const float* Wp2  = (const float*)d_in[6];
    const float* bp2  = (const float*)d_in[7];
    const float* lnw  = (const float*)d_in[8];
    const float* lnb  = (const float*)d_in[9];
    float* out = (float*)d_out;

    k_qproj  <<<256, 128>>>(q, Wkv);
    k_logits <<<SEQ / LROWS, 256>>>(x);
    {
        dim3 grid(4, NCH);
        k_wsum<<<grid, 256>>>(x);
    }
    {
        dim3 grid(H * DIM / 4 / 256, CSPLIT);
        k_ured<<<grid, 256>>>();
    }
    k_xv     <<<DIM / 4, 128>>>(Wkv, bkv);
    k_mlp1   <<<PDIM / 8, 256>>>(Wp1, bp1);
    k_mlp2   <<<DIM / 8, 256>>>(lnw, lnb, Wp2, bp2);
    k_resid  <<<SEQ * DIM / 4 / 512, 256>>>(x, out);
}

// round 16
// speedup vs baseline: 1.0426x; 1.0426x over previous
#include <cuda_runtime.h>
#include <cuda_bf16.h>

#define SEQ   8192
#define DIM   2048
#define H     16
#define HD    128           // head dim
#define PDIM  512           // proj dim
#define NCH   64            // weighted-sum chunks (128 rows each)
#define WROWS 128           // rows per wsum chunk
#define LROWS 32            // rows per logits block
#define NSEG  (SEQ / LROWS) // softmax partial segments = 256
#define CSPLIT 8            // k_ured chunk-split factor

// ---------------- scratch (device globals; no allocation allowed) ----------
__device__ float g_qprojH[H * DIM];          // [h][j], pre-scaled by 1/sqrt(HD)
__device__ float g_logits[SEQ * H];          // [s][h]
__device__ float g_pm[NSEG * H];             // per-seg max
__device__ float g_pz[NSEG * H];             // per-seg sumexp
__device__ float g_upart[(size_t)NCH * H * DIM]; // per-chunk weighted sums
__device__ float g_u2[CSPLIT * H * DIM];     // 8-way partial u
__device__ float g_x1[DIM];
__device__ float g_h1[PDIM];
__device__ float g_x1out[DIM];

// ---------------- f32x2 packed helpers -------------------------------------
union F2U { unsigned long long u; float2 f; };

__device__ __forceinline__ void ffma2(unsigned long long& d,
                                      unsigned long long a,
                                      unsigned long long b) {
    asm("fma.rn.f32x2 %0, %1, %2, %0;" : "+l"(d) : "l"(a), "l"(b));
}
__device__ __forceinline__ void addf32x2(unsigned long long& d, unsigned long long a) {
    asm("add.rn.f32x2 %0, %0, %1;" : "+l"(d) : "l"(a));
}
__device__ __forceinline__ unsigned long long pack2(float lo, float hi) {
    unsigned long long r;
    asm("mov.b64 %0, {%1, %2};" : "=l"(r) : "f"(lo), "f"(hi));
    return r;
}
__device__ __forceinline__ float f4el(const float4& v, int e) {
    return e == 0 ? v.x : e == 1 ? v.y : e == 2 ? v.z : v.w;
}
__device__ __forceinline__ float4 add4(float4 a, float4 b) {
    return make_float4(a.x + b.x, a.y + b.y, a.z + b.z, a.w + b.w);
}

__device__ __forceinline__ float blockReduceSum(float v) {
    __shared__ float sm[32];
    __syncthreads();
    int lane = threadIdx.x & 31, w = threadIdx.x >> 5;
    #pragma unroll
    for (int o = 16; o > 0; o >>= 1) v += __shfl_xor_sync(0xffffffffu, v, o);
    if (lane == 0) sm[w] = v;
    __syncthreads();
    int nw = blockDim.x >> 5;
    v = (threadIdx.x < nw) ? sm[threadIdx.x] : 0.f;
    if (w == 0) {
        #pragma unroll
        for (int o = 16; o > 0; o >>= 1) v += __shfl_xor_sync(0xffffffffu, v, o);
        if (lane == 0) sm[0] = v;
    }
    __syncthreads();
    return sm[0];
}

__device__ __forceinline__ float warpReduceSum(float v) {
    #pragma unroll
    for (int o = 16; o > 0; o >>= 1) v += __shfl_xor_sync(0xffffffffu, v, o);
    return v;
}

// ---------------- K1: qprojH[h][j] = (1/sqrt(HD)) * q[h] . W_k[h][:,j] -----
// unroll 32 -> 32 LDGs in flight per wave (4 waves instead of 16)
__global__ void k_qproj(const float* __restrict__ q, const float* __restrict__ Wkv) {
    int h  = blockIdx.x >> 4;
    int jb = blockIdx.x & 15;
    int j  = jb * 128 + threadIdx.x;
    __shared__ float sq[HD];
    sq[threadIdx.x] = q[h * HD + threadIdx.x];
    __syncthreads();
    float acc = 0.f;
    #pragma unroll 32
    for (int d = 0; d < HD; d++)
        acc += sq[d] * Wkv[(size_t)(h * HD + d) * DIM + j];
    g_qprojH[h * DIM + j] = acc * 0.08838834764831845f; // 1/sqrt(128)
}

// ---------------- K2: logits + per-block softmax partials ------------------
// 256 blocks x 256 threads. 8 warps = 4 warp-pairs; pair owns 8 rows;
// warp covers 8 heads. qproj pre-duplicated (w,w) in smem [h][e][lane]
// -> conflict-free LDS.64 feeding 4 FFMA2 each, zero repack. (R11/R14 version)
__global__ void __launch_bounds__(256, 2) k_logits(const float* __restrict__ x) {
    __shared__ float2 qs2[H][4][32];    // 16 KB per 128-col tile
    __shared__ float spm[8][8], spz[8][8];
    int t = threadIdx.x, lane = t & 31, warp = t >> 5;
    int pair = warp >> 1, hbase = (warp & 1) * 8;
    int row0 = blockIdx.x * LROWS + pair * 8;

    unsigned long long acc[8][4];       // [head][row-pair]
    #pragma unroll
    for (int hh = 0; hh < 8; hh++)
        #pragma unroll
        for (int p = 0; p < 4; p++) acc[hh][p] = 0ull;

    const float4* x4 = (const float4*)x;
    const float4* qp4 = (const float4*)g_qprojH;

    for (int jt4 = 0; jt4 < DIM / 4; jt4 += 32) {   // 16 tiles of 128 cols
        __syncthreads();
        #pragma unroll
        for (int r = 0; r < 2; r++) {
            int idx = t + r * 256;      // 0..511 -> (h, 32 float4)
            int h = idx >> 5;
            int jj = idx & 31;
            float4 v = __ldg(qp4 + (size_t)h * (DIM / 4) + jt4 + jj);
            qs2[h][0][jj] = make_float2(v.x, v.x);
            qs2[h][1][jj] = make_float2(v.y, v.y);
            qs2[h][2][jj] = make_float2(v.z, v.z);
            qs2[h][3][jj] = make_float2(v.w, v.w);
        }
        __syncthreads();
        float4 xv[8];
        #pragma unroll
        for (int rr = 0; rr < 8; rr++)
            xv[rr] = __ldg(x4 + (size_t)(row0 + rr) * (DIM / 4) + jt4 + lane);
        #pragma unroll
        for (int e = 0; e < 4; e++) {
            unsigned long long xp[4];
            #pragma unroll
            for (int p = 0; p < 4; p++)
                xp[p] = pack2(f4el(xv[2 * p], e), f4el(xv[2 * p + 1], e));
            #pragma unroll
            for (int hh = 0; hh < 8; hh++) {
                unsigned long long wp =
                    *(const unsigned long long*)&qs2[hbase + hh][e][lane]; // LDS.64
                ffma2(acc[hh][0], wp, xp[0]);
                ffma2(acc[hh][1], wp, xp[1]);
                ffma2(acc[hh][2], wp, xp[2]);
                ffma2(acc[hh][3], wp, xp[3]);
            }
        }
    }
    // shuffle-reduce; lane hh keeps head hbase+hh's 4 row-pairs
    unsigned long long keep[4];
    #pragma unroll
    for (int p = 0; p < 4; p++) keep[p] = 0ull;
    #pragma unroll
    for (int hh = 0; hh < 8; hh++) {
        unsigned long long v0 = acc[hh][0], v1 = acc[hh][1];
        unsigned long long v2 = acc[hh][2], v3 = acc[hh][3];
        #pragma unroll
        for (int o = 16; o > 0; o >>= 1) {
            addf32x2(v0, __shfl_xor_sync(0xffffffffu, v0, o));
            addf32x2(v1, __shfl_xor_sync(0xffffffffu, v1, o));
            addf32x2(v2, __shfl_xor_sync(0xffffffffu, v2, o));
            addf32x2(v3, __shfl_xor_sync(0xffffffffu, v3, o));
        }
        if (lane == hh) { keep[0] = v0; keep[1] = v1; keep[2] = v2; keep[3] = v3; }
    }
    if (lane < 8) {
        int h = hbase + lane;
        float r[8];
        #pragma unroll
        for (int p = 0; p < 4; p++) {
            F2U u; u.u = keep[p];
            r[2 * p] = u.f.x; r[2 * p + 1] = u.f.y;
        }
        float m = r[0];
        #pragma unroll
        for (int rr = 1; rr < 8; rr++) m = fmaxf(m, r[rr]);
        float z = 0.f;
        #pragma unroll
        for (int rr = 0; rr < 8; rr++) {
            g_logits[(size_t)(row0 + rr) * H + h] = r[rr];
            z += __expf(r[rr] - m);
        }
        spm[warp][lane] = m;
        spz[warp][lane] = z;
    }
    __syncthreads();
    if (t < H) {                        // merge 4 pairs -> per-block partial
        int hgc = t >> 3, hl = t & 7;
        float m = -3.0e38f, z = 0.f;
        #pragma unroll
        for (int p = 0; p < 4; p++) {
            int w = p * 2 + hgc;
            float mw = spm[w][hl], zw = spz[w][hl];
            float nm = fmaxf(m, mw);
            z = z * __expf(m - nm) + zw * __expf(mw - nm);
            m = nm;
        }
        g_pm[blockIdx.x * H + t] = m;
        g_pz[blockIdx.x * H + t] = z;
    }
}

// ---------------- K3: u_part[c][h][j] = sum_{s in chunk} attn[s][h]*x[s][j]
// grid (4, 64): blockIdx.x = (head-half<<1)|col-tile; 256 threads, 8 heads
// per block; 3 blocks/SM via launch_bounds. 2 rows/iter inner loop.
__global__ void __launch_bounds__(256, 3) k_wsum(const float* __restrict__ x) {
    __shared__ float sa[WROWS * H];     // 128 x 16 = 8 KB normalized weights
    __shared__ float sm_m[H], sm_inv[H];
    __shared__ float cm[256], cz[256];
    int t = threadIdx.x;
    int cx = blockIdx.x & 1, hg = blockIdx.x >> 1, hbase = hg * 8;

    // stage 1: each thread merges NSEG/16 = 16 segment partials for one head
    {
        int h = t & 15, grp = t >> 4;
        float m = -3.0e38f, z = 0.f;
        #pragma unroll 4
        for (int k = 0; k < NSEG / 16; k++) {
            int seg = grp * (NSEG / 16) + k;
            float mw = g_pm[seg * H + h], zw = g_pz[seg * H + h];
            float nm = fmaxf(m, mw);
            z = z * __expf(m - nm) + zw * __expf(mw - nm);
            m = nm;
        }
        cm[t] = m; cz[t] = z;
    }
    __syncthreads();
    if (t < H) {                        // stage 2: merge the 16 groups
        float m = cm[t], z = cz[t];
        #pragma unroll
        for (int g = 1; g < 16; g++) {
            float mw = cm[g * 16 + t], zw = cz[g * 16 + t];
            float nm = fmaxf(m, mw);
            z = z * __expf(m - nm) + zw * __expf(mw - nm);
            m = nm;
        }
        sm_m[t] = m; sm_inv[t] = 1.f / z;
    }
    __syncthreads();

    int s0 = blockIdx.y * WROWS;
    #pragma unroll
    for (int k = 0; k < 2; k++) {       // weights: 2048 floats = 512 float4
        int idx = t + k * 256;
        float4 l = __ldg((const float4*)(g_logits + (size_t)s0 * H) + idx);
        int h0 = (idx & 3) * 4;
        float4 w;
        w.x = __expf(l.x - sm_m[h0 + 0]) * sm_inv[h0 + 0];
        w.y = __expf(l.y - sm_m[h0 + 1]) * sm_inv[h0 + 1];
        w.z = __expf(l.z - sm_m[h0 + 2]) * sm_inv[h0 + 2];
        w.w = __expf(l.w - sm_m[h0 + 3]) * sm_inv[h0 + 3];
        ((float4*)sa)[idx] = w;
    }
    __syncthreads();

    int j4 = cx * 256 + t;
    unsigned long long acc[4][4];       // [head-pair within half][component]
    #pragma unroll
    for (int hp = 0; hp < 4; hp++)
        #pragma unroll
        for (int c = 0; c < 4; c++) acc[hp][c] = 0ull;

    const float4* x4 = (const float4*)x;
    #pragma unroll 2
    for (int r = 0; r < WROWS; r += 2) {
        float4 xa = __ldg(x4 + (size_t)(s0 + r + 0) * (DIM / 4) + j4);
        float4 xb = __ldg(x4 + (size_t)(s0 + r + 1) * (DIM / 4) + j4);
        unsigned long long xpa[4], xpb[4];
        xpa[0] = pack2(xa.x, xa.x); xpb[0] = pack2(xb.x, xb.x);
        xpa[1] = pack2(xa.y, xa.y); xpb[1] = pack2(xb.y, xb.y);
        xpa[2] = pack2(xa.z, xa.z); xpb[2] = pack2(xb.z, xb.z);
        xpa[3] = pack2(xa.w, xa.w); xpb[3] = pack2(xb.w, xb.w);
        const float2* ar0 = (const float2*)(sa + (r + 0) * H + hbase);
        const float2* ar1 = (const float2*)(sa + (r + 1) * H + hbase);
        #pragma unroll
        for (int hp = 0; hp < 4; hp++) {
            float2 a0 = ar0[hp];        // broadcast LDS.64
            float2 a1 = ar1[hp];
            unsigned long long ap0 = pack2(a0.x, a0.y);
            unsigned long long ap1 = pack2(a1.x, a1.y);
            ffma2(acc[hp][0], ap0, xpa[0]);
            ffma2(acc[hp][1], ap0, xpa[1]);
            ffma2(acc[hp][2], ap0, xpa[2]);
            ffma2(acc[hp][3], ap0, xpa[3]);
            ffma2(acc[hp][0], ap1, xpb[0]);
            ffma2(acc[hp][1], ap1, xpb[1]);
            ffma2(acc[hp][2], ap1, xpb[2]);
            ffma2(acc[hp][3], ap1, xpb[3]);
        }
    }
    float* up = g_upart + (size_t)blockIdx.y * (H * DIM);
    #pragma unroll
    for (int hp = 0; hp < 4; hp++) {
        F2U u0, u1, u2, u3;
        u0.u = acc[hp][0]; u1.u = acc[hp][1]; u2.u = acc[hp][2]; u3.u = acc[hp][3];
        float4 lo = make_float4(u0.f.x, u1.f.x, u2.f.x, u3.f.x);
        float4 hi = make_float4(u0.f.y, u1.f.y, u2.f.y, u3.f.y);
        ((float4*)(up + (size_t)(hbase + 2 * hp + 0) * DIM))[j4] = lo;
        ((float4*)(up + (size_t)(hbase + 2 * hp + 1) * DIM))[j4] = hi;
    }
}

// ---------------- K4: u2[p][i4] = sum_{c in part p} u_part[c][i4] ----------
// grid (32, CSPLIT=8) x 256 threads; 8 explicit float4 temps -> all loads
// issued back-to-back (MLP=8), then tree add.
__global__ void __launch_bounds__(256) k_ured() {
    int i4 = blockIdx.x * 256 + threadIdx.x;   // float4 index 0..H*DIM/4-1
    size_t base = (size_t)blockIdx.y * (NCH / CSPLIT) * (H * DIM / 4) + i4;
    const float4* up4 = (const float4*)g_upart;
    const size_t stride = H * DIM / 4;
    float4 v0 = up4[base + 0 * stride];
    float4 v1 = up4[base + 1 * stride];
    float4 v2 = up4[base + 2 * stride];
    float4 v3 = up4[base + 3 * stride];
    float4 v4 = up4[base + 4 * stride];
    float4 v5 = up4[base + 5 * stride];
    float4 v6 = up4[base + 6 * stride];
    float4 v7 = up4[base + 7 * stride];
    float4 s = add4(add4(add4(v0, v1), add4(v2, v3)),
                    add4(add4(v4, v5), add4(v6, v7)));
    ((float4*)g_u2)[(size_t)blockIdx.y * stride + i4] = s;
}

// ---------------- K5: x1[r] = b_v[r] + W_v[r] . u[r>>7] --------------------
__global__ void __launch_bounds__(128) k_xv(const float* __restrict__ Wkv,
                                            const float* __restrict__ bkv) {
    __shared__ float su[DIM];
    int t = threadIdx.x, lane = t & 31, warp = t >> 5;
    int r0 = blockIdx.x * 4;
    int h  = r0 >> 7;                   // 4 | 128 so all rows share the head
    #pragma unroll
    for (int i = 0; i < 4; i++) {
        int idx = t + i * 128;          // 512 float4 total
        float4 s = make_float4(0.f, 0.f, 0.f, 0.f);
        #pragma unroll
        for (int p = 0; p < CSPLIT; p++) {
            float4 a = *((const float4*)(g_u2 + (size_t)p * (H * DIM)
                                         + (size_t)h * DIM) + idx);
            s.x += a.x; s.y += a.y; s.z += a.z; s.w += a.w;
        }
        ((float4*)su)[idx] = s;
    }
    __syncthreads();
    int r = r0 + warp;
    const float4* w4 = (const float4*)(Wkv + (size_t)(DIM + r) * DIM);
    float acc = 0.f;
    #pragma unroll
    for (int i = 0; i < 16; i++) {
        float4 a = __ldg(w4 + i * 32 + lane);
        float4 b = ((float4*)su)[i * 32 + lane];
        acc += a.x * b.x + a.y * b.y + a.z * b.z + a.w * b.w;
    }
    acc = warpReduceSum(acc);
    if (lane == 0) g_x1[r] = acc + bkv[DIM + r];
}

// ---------------- K6: h1[r] = b_p1[r] + W_p1[r] . x1 -----------------------
__global__ void __launch_bounds__(256) k_mlp1(const float* __restrict__ Wp1,
                                              const float* __restrict__ bp1) {
    __shared__ float sv[DIM];
    int t = threadIdx.x, lane = t & 31, warp = t >> 5;
    #pragma unroll
    for (int i = 0; i < 2; i++)
        ((float4*)sv)[t + i * 256] = *((const float4*)g_x1 + t + i * 256);
    __syncthreads();
    int r = blockIdx.x * 8 + warp;
    const float4* w4 = (const float4*)(Wp1 + (size_t)r * DIM);
    float acc = 0.f;
    #pragma unroll
    for (int i = 0; i < 16; i++) {
        float4 a = __ldg(w4 + i * 32 + lane);
        float4 b = ((float4*)sv)[i * 32 + lane];
        acc += a.x * b.x + a.y * b.y + a.z * b.z + a.w * b.w;
    }
    acc = warpReduceSum(acc);
    if (lane == 0) g_h1[r] = acc + bp1[r];
}

// ---------------- K7: LN(h1) -> relu -> x1out = W_p2 . g + b_p2 ------------
__global__ void __launch_bounds__(256) k_mlp2(const float* __restrict__ lnw,
                                              const float* __restrict__ lnb,
                                              const float* __restrict__ Wp2,
                                              const float* __restrict__ bp2) {
    __shared__ float sg[PDIM];
    int t = threadIdx.x, lane = t & 31, warp = t >> 5;
    float v0 = g_h1[t], v1 = g_h1[t + 256];
    float mu = blockReduceSum(v0 + v1) * (1.f / PDIM);
    float d0 = v0 - mu, d1 = v1 - mu;
    float var = blockReduceSum(d0 * d0 + d1 * d1) * (1.f / PDIM);
    float rs = rsqrtf(var + 1e-5f);
    sg[t]       = fmaxf(d0 * rs * lnw[t]       + lnb[t],       0.f);
    sg[t + 256] = fmaxf(d1 * rs * lnw[t + 256] + lnb[t + 256], 0.f);
    __syncthreads();
    int r = blockIdx.x * 8 + warp;
    const float4* w4 = (const float4*)(Wp2 + (size_t)r * PDIM);
    float acc = 0.f;
    #pragma unroll
    for (int i = 0; i < 4; i++) {
        float4 a = __ldg(w4 + i * 32 + lane);
        float4 b = ((float4*)sg)[i * 32 + lane];
        acc += a.x * b.x + a.y * b.y + a.z * b.z + a.w * b.w;
    }
    acc = warpReduceSum(acc);
    if (lane == 0) g_x1out[r] = acc + bp2[r];
}

// ---------------- K8: out[s][j] = x[s][j] + x1out[j] -----------------------
__global__ void k_resid(const float* __restrict__ x, float* __restrict__ out) {
    size_t base = (size_t)blockIdx.x * 512 + threadIdx.x;
    #pragma unroll
    for (int r = 0; r < 2; r++) {
        size_t i = base + r * 256;
        float4 xv = ((const float4*)x)[i];
        float4 a  = __ldg((const float4*)g_x1out + (i & (DIM / 4 - 1)));
        xv.x += a.x; xv.y += a.y; xv.z += a.z; xv.w += a.w;
        ((float4*)out)[i] = xv;
    }
}

extern "C" void kernel_launch(void* const* d_in, const int* in_sizes, int n_in,
                              void* d_out, int out_size) {
    const float* x    = (const float*)d_in[0];
    const float* q    = (const float*)d_in[1];
    const float* Wkv  = (const float*)d_in[2];
    const float* bkv  = (const float*)d_in[3];
    const float* Wp1  = (const float*)d_in[4];
    const float* bp1  = (const float*)d_in[5];
    const float* Wp2  = (const float*)d_in[6];
    const float* bp2  = (const float*)d_in[7];
    const float* lnw  = (const float*)d_in[8];
    const float* lnb  = (const float*)d_in[9];
    float* out = (float*)d_out;

    k_qproj  <<<256, 128>>>(q, Wkv);
    k_logits <<<SEQ / LROWS, 256>>>(x);
    {
        dim3 grid(4, NCH);
        k_wsum<<<grid, 256>>>(x);
    }
    {
        dim3 grid(H * DIM / 4 / 256, CSPLIT);
        k_ured<<<grid, 256>>>();
    }
    k_xv     <<<DIM / 4, 128>>>(Wkv, bkv);
    k_mlp1   <<<PDIM / 8, 256>>>(Wp1, bp1);
    k_mlp2   <<<DIM / 8, 256>>>(lnw, lnb, Wp2, bp2);
    k_resid  <<<SEQ * DIM / 4 / 512, 256>>>(x, out);
}

// round 17
// speedup vs baseline: 1.0502x; 1.0073x over previous
#include <cuda_runtime.h>
#include <cuda_bf16.h>

#define SEQ   8192
#define DIM   2048
#define H     16
#define HD    128           // head dim
#define PDIM  512           // proj dim
#define NCH   64            // weighted-sum chunks (128 rows each)
#define WROWS 128           // rows per wsum chunk
#define LROWS 32            // rows per logits block
#define NSEG  (SEQ / LROWS) // softmax partial segments = 256
#define CSPLIT 8            // k_ured chunk-split factor

// ---------------- scratch (device globals; no allocation allowed) ----------
__device__ float g_qprojH[H * DIM];          // [h][j], pre-scaled by 1/sqrt(HD)
__device__ float g_logits[SEQ * H];          // [s][h]
__device__ float g_pm[NSEG * H];             // per-seg max
__device__ float g_pz[NSEG * H];             // per-seg sumexp
__device__ float g_upart[(size_t)NCH * H * DIM]; // per-chunk weighted sums
__device__ float g_u2[CSPLIT * H * DIM];     // 8-way partial u
__device__ float g_x1[DIM];
__device__ float g_h1[PDIM];
__device__ float g_x1out[DIM];

// ---------------- f32x2 packed helpers -------------------------------------
union F2U { unsigned long long u; float2 f; };

__device__ __forceinline__ void ffma2(unsigned long long& d,
                                      unsigned long long a,
                                      unsigned long long b) {
    asm("fma.rn.f32x2 %0, %1, %2, %0;" : "+l"(d) : "l"(a), "l"(b));
}
__device__ __forceinline__ void addf32x2(unsigned long long& d, unsigned long long a) {
    asm("add.rn.f32x2 %0, %0, %1;" : "+l"(d) : "l"(a));
}
__device__ __forceinline__ unsigned long long pack2(float lo, float hi) {
    unsigned long long r;
    asm("mov.b64 %0, {%1, %2};" : "=l"(r) : "f"(lo), "f"(hi));
    return r;
}
__device__ __forceinline__ float f4el(const float4& v, int e) {
    return e == 0 ? v.x : e == 1 ? v.y : e == 2 ? v.z : v.w;
}
__device__ __forceinline__ float4 add4(float4 a, float4 b) {
    return make_float4(a.x + b.x, a.y + b.y, a.z + b.z, a.w + b.w);
}
// asm load: result registers must materialize -> ptxas cannot serialize batch
__device__ __forceinline__ float4 ldg4(const float4* p) {
    float4 v;
    asm volatile("ld.global.nc.v4.f32 {%0, %1, %2, %3}, [%4];"
                 : "=f"(v.x), "=f"(v.y), "=f"(v.z), "=f"(v.w) : "l"(p));
    return v;
}

__device__ __forceinline__ float blockReduceSum(float v) {
    __shared__ float sm[32];
    __syncthreads();
    int lane = threadIdx.x & 31, w = threadIdx.x >> 5;
    #pragma unroll
    for (int o = 16; o > 0; o >>= 1) v += __shfl_xor_sync(0xffffffffu, v, o);
    if (lane == 0) sm[w] = v;
    __syncthreads();
    int nw = blockDim.x >> 5;
    v = (threadIdx.x < nw) ? sm[threadIdx.x] : 0.f;
    if (w == 0) {
        #pragma unroll
        for (int o = 16; o > 0; o >>= 1) v += __shfl_xor_sync(0xffffffffu, v, o);
        if (lane == 0) sm[0] = v;
    }
    __syncthreads();
    return sm[0];
}

__device__ __forceinline__ float warpReduceSum(float v) {
    #pragma unroll
    for (int o = 16; o > 0; o >>= 1) v += __shfl_xor_sync(0xffffffffu, v, o);
    return v;
}

// ---------------- K1: qprojH[h][j] = (1/sqrt(HD)) * q[h] . W_k[h][:,j] -----
__global__ void k_qproj(const float* __restrict__ q, const float* __restrict__ Wkv) {
    int h  = blockIdx.x >> 4;
    int jb = blockIdx.x & 15;
    int j  = jb * 128 + threadIdx.x;
    __shared__ float sq[HD];
    sq[threadIdx.x] = q[h * HD + threadIdx.x];
    __syncthreads();
    float acc = 0.f;
    #pragma unroll 32
    for (int d = 0; d < HD; d++)
        acc += sq[d] * Wkv[(size_t)(h * HD + d) * DIM + j];
    g_qprojH[h * DIM + j] = acc * 0.08838834764831845f; // 1/sqrt(128)
}

// ---------------- K2: logits + per-block softmax partials ------------------
// 256 blocks x 256 threads. 8 warps = 4 warp-pairs; pair owns 8 rows;
// warp covers 8 heads. qproj pre-duplicated (w,w) in smem [h][e][lane].
__global__ void __launch_bounds__(256, 2) k_logits(const float* __restrict__ x) {
    __shared__ float2 qs2[H][4][32];    // 16 KB per 128-col tile
    __shared__ float spm[8][8], spz[8][8];
    int t = threadIdx.x, lane = t & 31, warp = t >> 5;
    int pair = warp >> 1, hbase = (warp & 1) * 8;
    int row0 = blockIdx.x * LROWS + pair * 8;

    unsigned long long acc[8][4];       // [head][row-pair]
    #pragma unroll
    for (int hh = 0; hh < 8; hh++)
        #pragma unroll
        for (int p = 0; p < 4; p++) acc[hh][p] = 0ull;

    const float4* x4 = (const float4*)x;
    const float4* qp4 = (const float4*)g_qprojH;

    for (int jt4 = 0; jt4 < DIM / 4; jt4 += 32) {   // 16 tiles of 128 cols
        __syncthreads();
        #pragma unroll
        for (int r = 0; r < 2; r++) {
            int idx = t + r * 256;      // 0..511 -> (h, 32 float4)
            int h = idx >> 5;
            int jj = idx & 31;
            float4 v = __ldg(qp4 + (size_t)h * (DIM / 4) + jt4 + jj);
            qs2[h][0][jj] = make_float2(v.x, v.x);
            qs2[h][1][jj] = make_float2(v.y, v.y);
            qs2[h][2][jj] = make_float2(v.z, v.z);
            qs2[h][3][jj] = make_float2(v.w, v.w);
        }
        __syncthreads();
        float4 xv[8];
        #pragma unroll
        for (int rr = 0; rr < 8; rr++)
            xv[rr] = __ldg(x4 + (size_t)(row0 + rr) * (DIM / 4) + jt4 + lane);
        #pragma unroll
        for (int e = 0; e < 4; e++) {
            unsigned long long xp[4];
            #pragma unroll
            for (int p = 0; p < 4; p++)
                xp[p] = pack2(f4el(xv[2 * p], e), f4el(xv[2 * p + 1], e));
            #pragma unroll
            for (int hh = 0; hh < 8; hh++) {
                unsigned long long wp =
                    *(const unsigned long long*)&qs2[hbase + hh][e][lane]; // LDS.64
                ffma2(acc[hh][0], wp, xp[0]);
                ffma2(acc[hh][1], wp, xp[1]);
                ffma2(acc[hh][2], wp, xp[2]);
                ffma2(acc[hh][3], wp, xp[3]);
            }
        }
    }
    // shuffle-reduce; lane hh keeps head hbase+hh's 4 row-pairs
    unsigned long long keep[4];
    #pragma unroll
    for (int p = 0; p < 4; p++) keep[p] = 0ull;
    #pragma unroll
    for (int hh = 0; hh < 8; hh++) {
        unsigned long long v0 = acc[hh][0], v1 = acc[hh][1];
        unsigned long long v2 = acc[hh][2], v3 = acc[hh][3];
        #pragma unroll
        for (int o = 16; o > 0; o >>= 1) {
            addf32x2(v0, __shfl_xor_sync(0xffffffffu, v0, o));
            addf32x2(v1, __shfl_xor_sync(0xffffffffu, v1, o));
            addf32x2(v2, __shfl_xor_sync(0xffffffffu, v2, o));
            addf32x2(v3, __shfl_xor_sync(0xffffffffu, v3, o));
        }
        if (lane == hh) { keep[0] = v0; keep[1] = v1; keep[2] = v2; keep[3] = v3; }
    }
    if (lane < 8) {
        int h = hbase + lane;
        float r[8];
        #pragma unroll
        for (int p = 0; p < 4; p++) {
            F2U u; u.u = keep[p];
            r[2 * p] = u.f.x; r[2 * p + 1] = u.f.y;
        }
        float m = r[0];
        #pragma unroll
        for (int rr = 1; rr < 8; rr++) m = fmaxf(m, r[rr]);
        float z = 0.f;
        #pragma unroll
        for (int rr = 0; rr < 8; rr++) {
            g_logits[(size_t)(row0 + rr) * H + h] = r[rr];
            z += __expf(r[rr] - m);
        }
        spm[warp][lane] = m;
        spz[warp][lane] = z;
    }
    __syncthreads();
    if (t < H) {                        // merge 4 pairs -> per-block partial
        int hgc = t >> 3, hl = t & 7;
        float m = -3.0e38f, z = 0.f;
        #pragma unroll
        for (int p = 0; p < 4; p++) {
            int w = p * 2 + hgc;
            float mw = spm[w][hl], zw = spz[w][hl];
            float nm = fmaxf(m, mw);
            z = z * __expf(m - nm) + zw * __expf(mw - nm);
            m = nm;
        }
        g_pm[blockIdx.x * H + t] = m;
        g_pz[blockIdx.x * H + t] = z;
    }
}

// ---------------- K3: u_part[c][h][j] = sum_{s in chunk} attn[s][h]*x[s][j]
// grid (4, 64): blockIdx.x = (head-half<<1)|col-tile; 256 threads, 8 heads
// per block; 3 blocks/SM via launch_bounds. 2 rows/iter inner loop.
__global__ void __launch_bounds__(256, 3) k_wsum(const float* __restrict__ x) {
    __shared__ float sa[WROWS * H];     // 128 x 16 = 8 KB normalized weights
    __shared__ float sm_m[H], sm_inv[H];
    __shared__ float cm[256], cz[256];
    int t = threadIdx.x;
    int cx = blockIdx.x & 1, hg = blockIdx.x >> 1, hbase = hg * 8;

    // stage 1: each thread merges NSEG/16 = 16 segment partials for one head
    {
        int h = t & 15, grp = t >> 4;
        float m = -3.0e38f, z = 0.f;
        #pragma unroll 4
        for (int k = 0; k < NSEG / 16; k++) {
            int seg = grp * (NSEG / 16) + k;
            float mw = g_pm[seg * H + h], zw = g_pz[seg * H + h];
            float nm = fmaxf(m, mw);
            z = z * __expf(m - nm) + zw * __expf(mw - nm);
            m = nm;
        }
        cm[t] = m; cz[t] = z;
    }
    __syncthreads();
    if (t < H) {                        // stage 2: merge the 16 groups
        float m = cm[t], z = cz[t];
        #pragma unroll
        for (int g = 1; g < 16; g++) {
            float mw = cm[g * 16 + t], zw = cz[g * 16 + t];
            float nm = fmaxf(m, mw);
            z = z * __expf(m - nm) + zw * __expf(mw - nm);
            m = nm;
        }
        sm_m[t] = m; sm_inv[t] = 1.f / z;
    }
    __syncthreads();

    int s0 = blockIdx.y * WROWS;
    #pragma unroll
    for (int k = 0; k < 2; k++) {       // weights: 2048 floats = 512 float4
        int idx = t + k * 256;
        float4 l = __ldg((const float4*)(g_logits + (size_t)s0 * H) + idx);
        int h0 = (idx & 3) * 4;
        float4 w;
        w.x = __expf(l.x - sm_m[h0 + 0]) * sm_inv[h0 + 0];
        w.y = __expf(l.y - sm_m[h0 + 1]) * sm_inv[h0 + 1];
        w.z = __expf(l.z - sm_m[h0 + 2]) * sm_inv[h0 + 2];
        w.w = __expf(l.w - sm_m[h0 + 3]) * sm_inv[h0 + 3];
        ((float4*)sa)[idx] = w;
    }
    __syncthreads();

    int j4 = cx * 256 + t;
    unsigned long long acc[4][4];       // [head-pair within half][component]
    #pragma unroll
    for (int hp = 0; hp < 4; hp++)
        #pragma unroll
        for (int c = 0; c < 4; c++) acc[hp][c] = 0ull;

    const float4* x4 = (const float4*)x;
    #pragma unroll 2
    for (int r = 0; r < WROWS; r += 2) {
        float4 xa = __ldg(x4 + (size_t)(s0 + r + 0) * (DIM / 4) + j4);
        float4 xb = __ldg(x4 + (size_t)(s0 + r + 1) * (DIM / 4) + j4);
        unsigned long long xpa[4], xpb[4];
        xpa[0] = pack2(xa.x, xa.x); xpb[0] = pack2(xb.x, xb.x);
        xpa[1] = pack2(xa.y, xa.y); xpb[1] = pack2(xb.y, xb.y);
        xpa[2] = pack2(xa.z, xa.z); xpb[2] = pack2(xb.z, xb.z);
        xpa[3] = pack2(xa.w, xa.w); xpb[3] = pack2(xb.w, xb.w);
        const float2* ar0 = (const float2*)(sa + (r + 0) * H + hbase);
        const float2* ar1 = (const float2*)(sa + (r + 1) * H + hbase);
        #pragma unroll
        for (int hp = 0; hp < 4; hp++) {
            float2 a0 = ar0[hp];        // broadcast LDS.64
            float2 a1 = ar1[hp];
            unsigned long long ap0 = pack2(a0.x, a0.y);
            unsigned long long ap1 = pack2(a1.x, a1.y);
            ffma2(acc[hp][0], ap0, xpa[0]);
            ffma2(acc[hp][1], ap0, xpa[1]);
            ffma2(acc[hp][2], ap0, xpa[2]);
            ffma2(acc[hp][3], ap0, xpa[3]);
            ffma2(acc[hp][0], ap1, xpb[0]);
            ffma2(acc[hp][1], ap1, xpb[1]);
            ffma2(acc[hp][2], ap1, xpb[2]);
            ffma2(acc[hp][3], ap1, xpb[3]);
        }
    }
    float* up = g_upart + (size_t)blockIdx.y * (H * DIM);
    #pragma unroll
    for (int hp = 0; hp < 4; hp++) {
        F2U u0, u1, u2, u3;
        u0.u = acc[hp][0]; u1.u = acc[hp][1]; u2.u = acc[hp][2]; u3.u = acc[hp][3];
        float4 lo = make_float4(u0.f.x, u1.f.x, u2.f.x, u3.f.x);
        float4 hi = make_float4(u0.f.y, u1.f.y, u2.f.y, u3.f.y);
        ((float4*)(up + (size_t)(hbase + 2 * hp + 0) * DIM))[j4] = lo;
        ((float4*)(up + (size_t)(hbase + 2 * hp + 1) * DIM))[j4] = hi;
    }
}

// ---------------- K4: u2[p][i4] = sum_{c in part p} u_part[c][i4] ----------
// grid (32, CSPLIT=8) x 256 threads; asm-forced 8-wide load batch (MLP=8)
__global__ void __launch_bounds__(256) k_ured() {
    int i4 = blockIdx.x * 256 + threadIdx.x;   // float4 index 0..H*DIM/4-1
    size_t base = (size_t)blockIdx.y * (NCH / CSPLIT) * (H * DIM / 4) + i4;
    const float4* up4 = (const float4*)g_upart;
    const size_t stride = H * DIM / 4;
    float4 v0 = ldg4(up4 + base + 0 * stride);
    float4 v1 = ldg4(up4 + base + 1 * stride);
    float4 v2 = ldg4(up4 + base + 2 * stride);
    float4 v3 = ldg4(up4 + base + 3 * stride);
    float4 v4 = ldg4(up4 + base + 4 * stride);
    float4 v5 = ldg4(up4 + base + 5 * stride);
    float4 v6 = ldg4(up4 + base + 6 * stride);
    float4 v7 = ldg4(up4 + base + 7 * stride);
    float4 s = add4(add4(add4(v0, v1), add4(v2, v3)),
                    add4(add4(v4, v5), add4(v6, v7)));
    ((float4*)g_u2)[(size_t)blockIdx.y * stride + i4] = s;
}

// ---------------- K5: x1[r] = b_v[r] + W_v[r] . u[r>>7] --------------------
// asm-forced 8-wide staging loads (MLP=8 per index)
__global__ void __launch_bounds__(128) k_xv(const float* __restrict__ Wkv,
                                            const float* __restrict__ bkv) {
    __shared__ float su[DIM];
    int t = threadIdx.x, lane = t & 31, warp = t >> 5;
    int r0 = blockIdx.x * 4;
    int h  = r0 >> 7;                   // 4 | 128 so all rows share the head
    const float4* u2b = (const float4*)(g_u2) + (size_t)h * (DIM / 4);
    const size_t pst = H * DIM / 4;
    #pragma unroll
    for (int i = 0; i < 4; i++) {
        int idx = t + i * 128;          // 512 float4 total
        float4 v0 = ldg4(u2b + 0 * pst + idx);
        float4 v1 = ldg4(u2b + 1 * pst + idx);
        float4 v2 = ldg4(u2b + 2 * pst + idx);
        float4 v3 = ldg4(u2b + 3 * pst + idx);
        float4 v4 = ldg4(u2b + 4 * pst + idx);
        float4 v5 = ldg4(u2b + 5 * pst + idx);
        float4 v6 = ldg4(u2b + 6 * pst + idx);
        float4 v7 = ldg4(u2b + 7 * pst + idx);
        ((float4*)su)[idx] = add4(add4(add4(v0, v1), add4(v2, v3)),
                                  add4(add4(v4, v5), add4(v6, v7)));
    }
    __syncthreads();
    int r = r0 + warp;
    const float4* w4 = (const float4*)(Wkv + (size_t)(DIM + r) * DIM);
    float acc = 0.f;
    #pragma unroll
    for (int i = 0; i < 16; i++) {
        float4 a = __ldg(w4 + i * 32 + lane);
        float4 b = ((float4*)su)[i * 32 + lane];
        acc += a.x * b.x + a.y * b.y + a.z * b.z + a.w * b.w;
    }
    acc = warpReduceSum(acc);
    if (lane == 0) g_x1[r] = acc + bkv[DIM + r];
}

// ---------------- K6: h1[r] = b_p1[r] + W_p1[r] . x1 -----------------------
__global__ void __launch_bounds__(256) k_mlp1(const float* __restrict__ Wp1,
                                              const float* __restrict__ bp1) {
    __shared__ float sv[DIM];
    int t = threadIdx.x, lane = t & 31, warp = t >> 5;
    #pragma unroll
    for (int i = 0; i < 2; i++)
        ((float4*)sv)[t + i * 256] = *((const float4*)g_x1 + t + i * 256);
    __syncthreads();
    int r = blockIdx.x * 8 + warp;
    const float4* w4 = (const float4*)(Wp1 + (size_t)r * DIM);
    float acc = 0.f;
    #pragma unroll
    for (int i = 0; i < 16; i++) {
        float4 a = __ldg(w4 + i * 32 + lane);
        float4 b = ((float4*)sv)[i * 32 + lane];
        acc += a.x * b.x + a.y * b.y + a.z * b.z + a.w * b.w;
    }
    acc = warpReduceSum(acc);
    if (lane == 0) g_h1[r] = acc + bp1[r];
}

// ---------------- K7: LN(h1) -> relu -> x1out = W_p2 . g + b_p2 ------------
__global__ void __launch_bounds__(256) k_mlp2(const float* __restrict__ lnw,
                                              const float* __restrict__ lnb,
                                              const float* __restrict__ Wp2,
                                              const float* __restrict__ bp2) {
    __shared__ float sg[PDIM];
    int t = threadIdx.x, lane = t & 31, warp = t >> 5;
    float v0 = g_h1[t], v1 = g_h1[t + 256];
    float mu = blockReduceSum(v0 + v1) * (1.f / PDIM);
    float d0 = v0 - mu, d1 = v1 - mu;
    float var = blockReduceSum(d0 * d0 + d1 * d1) * (1.f / PDIM);
    float rs = rsqrtf(var + 1e-5f);
    sg[t]       = fmaxf(d0 * rs * lnw[t]       + lnb[t],       0.f);
    sg[t + 256] = fmaxf(d1 * rs * lnw[t + 256] + lnb[t + 256], 0.f);
    __syncthreads();
    int r = blockIdx.x * 8 + warp;
    const float4* w4 = (const float4*)(Wp2 + (size_t)r * PDIM);
    float acc = 0.f;
    #pragma unroll
    for (int i = 0; i < 4; i++) {
        float4 a = __ldg(w4 + i * 32 + lane);
        float4 b = ((float4*)sg)[i * 32 + lane];
        acc += a.x * b.x + a.y * b.y + a.z * b.z + a.w * b.w;
    }
    acc = warpReduceSum(acc);
    if (lane == 0) g_x1out[r] = acc + bp2[r];
}

// ---------------- K8: out[s][j] = x[s][j] + x1out[j] -----------------------
__global__ void k_resid(const float* __restrict__ x, float* __restrict__ out) {
    size_t base = (size_t)blockIdx.x * 512 + threadIdx.x;
    #pragma unroll
    for (int r = 0; r < 2; r++) {
        size_t i = base + r * 256;
        float4 xv = ((const float4*)x)[i];
        float4 a  = __ldg((const float4*)g_x1out + (i & (DIM / 4 - 1)));
        xv.x += a.x; xv.y += a.y; xv.z += a.z; xv.w += a.w;
        ((float4*)out)[i] = xv;
    }
}

extern "C" void kernel_launch(void* const* d_in, const int* in_sizes, int n_in,
                              void* d_out, int out_size) {
    const float* x    = (const float*)d_in[0];
    const float* q    = (const float*)d_in[1];
    const float* Wkv  = (const float*)d_in[2];
    const float* bkv  = (const float*)d_in[3];
    const float* Wp1  = (const float*)d_in[4];
    const float* bp1  = (const float*)d_in[5];
    const float* Wp2  = (const float*)d_in[6];
    const float* bp2  = (const float*)d_in[7];
    const float* lnw  = (const float*)d_in[8];
    const float* lnb  = (const float*)d_in[9];
    float* out = (float*)d_out;

    k_qproj  <<<256, 128>>>(q, Wkv);
    k_logits <<<SEQ / LROWS, 256>>>(x);
    {
        dim3 grid(4, NCH);
        k_wsum<<<grid, 256>>>(x);
    }
    {
        dim3 grid(H * DIM / 4 / 256, CSPLIT);
        k_ured<<<grid, 256>>>();
    }
    k_xv     <<<DIM / 4, 128>>>(Wkv, bkv);
    k_mlp1   <<<PDIM / 8, 256>>>(Wp1, bp1);
    k_mlp2   <<<DIM / 8, 256>>>(lnw, lnb, Wp2, bp2);
    k_resid  <<<SEQ * DIM / 4 / 512, 256>>>(x, out);
}